// round 8
// baseline (speedup 1.0000x reference)
#include <cuda_runtime.h>
#include <math.h>
#include <stdint.h>

// ---------------------------------------------------------------------------
// SoftMoE forward, tensor-core tf32 (m16n8k8, fp32 accum).
// R6 structure + free pre-rounding (cvt removal) + merged-M expert stages.
// Logits GEMM keeps the 3xTF32 split (fp32-grade) to protect argmax outputs.
// B=4, M=1024, D=768, E=16, P=64, F=3072.
// ---------------------------------------------------------------------------

namespace cfg {
constexpr int cB = 4, cM = 1024, cD = 768, cE = 16, cP = 64, cF = 3072;
constexpr int cEP = cE * cP;  // 1024
constexpr long long SZ_OUT  = (long long)cB * cM * cD;
constexpr long long SZ_PROB = (long long)cB * cM * cE;
constexpr long long SZ_TOP  = (long long)cB * cM;
constexpr long long SZ_HID  = (long long)cB * cE * cP * cF;
constexpr long long SZ_FULL = SZ_OUT + SZ_PROB + SZ_TOP + SZ_HID;
}
using namespace cfg;

// Scratch (allocation-free: __device__ globals).
__device__ float g_logits  [(size_t)cB * cM * cEP];
__device__ float g_dispatch[(size_t)cB * cM * cEP];
__device__ float g_combine [(size_t)cB * cM * cEP];
__device__ float g_mix     [(size_t)cB * cE * cP * cD];
__device__ float g_eout    [(size_t)cB * cE * cP * cD];
__device__ float g_hid_fb  [(size_t)cB * cE * cP * cF];  // fallback hidden

// ---------------------------------------------------------------------------
// PTX helpers
// ---------------------------------------------------------------------------
__device__ __forceinline__ void cp_async16(void* s, const void* g) {
    unsigned sa = (unsigned)__cvta_generic_to_shared(s);
    asm volatile("cp.async.ca.shared.global [%0], [%1], 16;\n" :: "r"(sa), "l"(g));
}
__device__ __forceinline__ void cp_async4(void* s, const void* g) {
    unsigned sa = (unsigned)__cvta_generic_to_shared(s);
    asm volatile("cp.async.ca.shared.global [%0], [%1], 4;\n" :: "r"(sa), "l"(g));
}
__device__ __forceinline__ void cp_commit() {
    asm volatile("cp.async.commit_group;\n");
}
template <int N>
__device__ __forceinline__ void cp_wait() {
    asm volatile("cp.async.wait_group %0;\n" :: "n"(N));
}

__device__ __forceinline__ uint32_t f2tf(float x) {
    uint32_t u;
    asm("cvt.rna.tf32.f32 %0, %1;" : "=r"(u) : "f"(x));
    return u;
}
__device__ __forceinline__ float round_tf(float x) {
    return __uint_as_float(f2tf(x));
}

__device__ __forceinline__ void mma_tf32(float c[4], const uint32_t a[4],
                                         const uint32_t b[2]) {
    asm volatile(
        "mma.sync.aligned.m16n8k8.row.col.f32.tf32.tf32.f32 "
        "{%0,%1,%2,%3}, {%4,%5,%6,%7}, {%8,%9}, {%0,%1,%2,%3};\n"
        : "+f"(c[0]), "+f"(c[1]), "+f"(c[2]), "+f"(c[3])
        : "r"(a[0]), "r"(a[1]), "r"(a[2]), "r"(a[3]),
          "r"(b[0]), "r"(b[1]));
}

__device__ __forceinline__ float gelu_tanh(float x) {
    float x3 = x * x * x;
    return 0.5f * x * (1.0f + tanhf(0.7978845608028654f * (x + 0.044715f * x3)));
}

// ---------------------------------------------------------------------------
// Tensor-core GEMM: C[Md,Nd] = op(A)[Md,Kd] * B[Kd,Nd] (+bias) (+gelu)
//   TM=128, TN=128, TK=16. 8 warps (2 x 4), warp tile 64x32.
//   Same smem layout and load paths as the proven R6 kernel.
// op(A)=A   row-major [Md,Kd]          when !TRANSA
// op(A)=A^T with A row-major [Kd,Md]   when TRANSA (Md is the row stride)
// SPLIT: 3xTF32 error-compensated pass (fp32-grade accuracy).
// ACVT/BCVT: convert operand to tf32 inline; false = operand pre-rounded,
//   feed raw fp32 bits (exact).
// ROUND: round C to tf32 in the epilogue (post-bias/activation).
// remapE>0: row r of A/C maps to global row ((r>>6)*remapE + z)*64 + (r&63)
//   (merges the 4 batches of expert z into M=256, b-major storage kept).
// Batched over blockIdx.z with strides sA_g/sB_g/sC_g/sBias_g.
// ---------------------------------------------------------------------------
#define TBM 128
#define TBN 128
#define TBK 16
#define SAS 136
#define SBS 136

template <bool TRANSA, int ACT, bool SPLIT, bool ACVT, bool BCVT, bool ROUND>
__global__ __launch_bounds__(256) void gemm_tc(
    const float* __restrict__ A, const float* __restrict__ B,
    float* __restrict__ C, const float* __restrict__ bias,
    int Md, int Nd, int Kd,
    long long sA_g, long long sB_g, long long sC_g, long long sBias_g,
    int remapE)
{
    constexpr int MI = 4;  // m16 tiles per warp (warp M = 64)
    constexpr int NI = 4;  // n8 tiles per warp (warp N = 32)

    const int gg = blockIdx.z;
    A += (long long)gg * sA_g;
    B += (long long)gg * sB_g;
    C += (long long)gg * sC_g;
    if (bias) bias += (long long)gg * sBias_g;

    __shared__ float As[2][TBK][SAS];
    __shared__ float Bs[2][TBK][SBS];

    const int tid  = threadIdx.x;
    const int lane = tid & 31, warp = tid >> 5;
    const int t  = lane & 3;
    const int gq = lane >> 2;
    const int wm = warp & 1, wn = warp >> 1;
    const int m_base = wm * 64;
    const int n_base = wn * 32;
    const int row0 = blockIdx.y * TBM;
    const int col0 = blockIdx.x * TBN;

    auto rowmap = [&](int r) -> long long {
        if (remapE > 0)
            return (long long)((r >> 6) * remapE + gg) * 64 + (r & 63);
        return r;
    };

    auto loadA = [&](int buf, int k0) {
        if (!TRANSA) {
            #pragma unroll
            for (int i = 0; i < (TBM * TBK) / 256; i++) {
                int l = tid + i * 256;
                int kk = l & 15, mm = l >> 4;
                cp_async4(&As[buf][kk][mm],
                          &A[rowmap(row0 + mm) * Kd + (k0 + kk)]);
            }
        } else {
            #pragma unroll
            for (int i = 0; i < (TBM * TBK) / 1024; i++) {
                int l = tid * 4 + i * 1024;
                int ii = l % TBM, kk = l / TBM;
                cp_async16(&As[buf][kk][ii],
                           &A[(long long)(k0 + kk) * Md + (row0 + ii)]);
            }
        }
    };
    auto loadB = [&](int buf, int k0) {
        #pragma unroll
        for (int i = 0; i < (TBN * TBK) / 1024; i++) {
            int l = tid * 4 + i * 1024;
            int nn = l % TBN, kk = l / TBN;
            cp_async16(&Bs[buf][kk][nn],
                       &B[(long long)(k0 + kk) * Nd + (col0 + nn)]);
        }
    };

    float acc[MI][NI][4];
    #pragma unroll
    for (int i = 0; i < MI; i++)
        #pragma unroll
        for (int j = 0; j < NI; j++)
            #pragma unroll
            for (int q = 0; q < 4; q++) acc[i][j][q] = 0.0f;

    loadA(0, 0);
    loadB(0, 0);
    cp_commit();

    const int nk = Kd / TBK;
    int buf = 0;
    for (int it = 0; it < nk; it++) {
        if (it + 1 < nk) {
            loadA(buf ^ 1, (it + 1) * TBK);
            loadB(buf ^ 1, (it + 1) * TBK);
            cp_commit();
            cp_wait<1>();
        } else {
            cp_wait<0>();
        }
        __syncthreads();

        #pragma unroll
        for (int ks = 0; ks < TBK; ks += 8) {
            uint32_t Ah[MI][4], Bh[NI][2];
            uint32_t Al[MI][4], Bl[NI][2];

            #pragma unroll
            for (int mi = 0; mi < MI; mi++) {
                const int m0 = m_base + mi * 16;
                float v[4];
                v[0] = As[buf][ks + t    ][m0 + gq];
                v[1] = As[buf][ks + t    ][m0 + gq + 8];
                v[2] = As[buf][ks + t + 4][m0 + gq];
                v[3] = As[buf][ks + t + 4][m0 + gq + 8];
                #pragma unroll
                for (int q = 0; q < 4; q++) {
                    Ah[mi][q] = (ACVT || SPLIT) ? f2tf(v[q])
                                                : __float_as_uint(v[q]);
                    if (SPLIT)
                        Al[mi][q] = f2tf(v[q] - __uint_as_float(Ah[mi][q]));
                }
            }
            #pragma unroll
            for (int ni = 0; ni < NI; ni++) {
                const int n0 = n_base + ni * 8;
                float u0 = Bs[buf][ks + t    ][n0 + gq];
                float u1 = Bs[buf][ks + t + 4][n0 + gq];
                Bh[ni][0] = (BCVT || SPLIT) ? f2tf(u0) : __float_as_uint(u0);
                Bh[ni][1] = (BCVT || SPLIT) ? f2tf(u1) : __float_as_uint(u1);
                if (SPLIT) {
                    Bl[ni][0] = f2tf(u0 - __uint_as_float(Bh[ni][0]));
                    Bl[ni][1] = f2tf(u1 - __uint_as_float(Bh[ni][1]));
                }
            }

            #pragma unroll
            for (int mi = 0; mi < MI; mi++)
                #pragma unroll
                for (int ni = 0; ni < NI; ni++) {
                    if (SPLIT) {
                        mma_tf32(acc[mi][ni], Ah[mi], Bl[ni]);
                        mma_tf32(acc[mi][ni], Al[mi], Bh[ni]);
                    }
                    mma_tf32(acc[mi][ni], Ah[mi], Bh[ni]);
                }
        }
        __syncthreads();
        buf ^= 1;
    }

    // Epilogue: c0,c1 at (r, 2t/2t+1); c2,c3 at (r+8, same cols)
    #pragma unroll
    for (int mi = 0; mi < MI; mi++) {
        const int r1 = row0 + m_base + mi * 16 + gq;
        const long long ra = rowmap(r1), rb2 = rowmap(r1 + 8);
        #pragma unroll
        for (int ni = 0; ni < NI; ni++) {
            const int cg = col0 + n_base + ni * 8 + 2 * t;
            float b0 = 0.0f, b1 = 0.0f;
            if (bias) { b0 = bias[cg]; b1 = bias[cg + 1]; }
            float v0 = acc[mi][ni][0] + b0;
            float v1 = acc[mi][ni][1] + b1;
            float v2 = acc[mi][ni][2] + b0;
            float v3 = acc[mi][ni][3] + b1;
            if (ACT == 1) {
                v0 = gelu_tanh(v0); v1 = gelu_tanh(v1);
                v2 = gelu_tanh(v2); v3 = gelu_tanh(v3);
            }
            if (ROUND) {
                v0 = round_tf(v0); v1 = round_tf(v1);
                v2 = round_tf(v2); v3 = round_tf(v3);
            }
            *reinterpret_cast<float2*>(&C[ra  * Nd + cg]) = make_float2(v0, v1);
            *reinterpret_cast<float2*>(&C[rb2 * Nd + cg]) = make_float2(v2, v3);
        }
    }
}

// ---------------------------------------------------------------------------
// dispatch = softmax over tokens m (axis 1); output tf32-rounded.
// ---------------------------------------------------------------------------
__global__ __launch_bounds__(256) void dispatch_softmax_kernel(
    const float* __restrict__ logits, float* __restrict__ dispatch)
{
    const int b = blockIdx.y;
    const int ep = blockIdx.x * 32 + threadIdx.x;
    const int tx = threadIdx.x, ty = threadIdx.y;
    const float* base = logits + (long long)b * cM * cEP + ep;
    float* obase = dispatch + (long long)b * cM * cEP + ep;

    float mx = -INFINITY, s = 0.0f;
    for (int m = ty; m < cM; m += 8) {
        float v = base[(long long)m * cEP];
        float nm = fmaxf(mx, v);
        s = s * expf(mx - nm) + expf(v - nm);
        mx = nm;
    }
    __shared__ float smx[8][32], ssum[8][32];
    smx[ty][tx] = mx;
    ssum[ty][tx] = s;
    __syncthreads();
    if (ty == 0) {
        float M_ = smx[0][tx], S = ssum[0][tx];
        #pragma unroll
        for (int i = 1; i < 8; i++) {
            float m2 = smx[i][tx];
            float nm = fmaxf(M_, m2);
            S = S * expf(M_ - nm) + ssum[i][tx] * expf(m2 - nm);
            M_ = nm;
        }
        smx[0][tx] = M_;
        ssum[0][tx] = 1.0f / S;
    }
    __syncthreads();
    const float gmx = smx[0][tx];
    const float inv = ssum[0][tx];
    for (int m = ty; m < cM; m += 8)
        obase[(long long)m * cEP] =
            round_tf(expf(base[(long long)m * cEP] - gmx) * inv);
}

// ---------------------------------------------------------------------------
// combine = softmax over ep (tf32-rounded) + probabilities + argmax (fp32).
// ---------------------------------------------------------------------------
__global__ __launch_bounds__(256) void combine_softmax_kernel(
    const float* __restrict__ logits, float* __restrict__ combine,
    float* __restrict__ prob, float* __restrict__ top)
{
    const long long bm = blockIdx.y * gridDim.x + blockIdx.x;
    const float* row = logits + bm * cEP;
    float* crow = combine + bm * cEP;

    __shared__ float sv[cEP];
    __shared__ float sred[8];
    __shared__ float sbc;
    __shared__ float sprob[cE];

    const int tid = threadIdx.x;
    const int lane = tid & 31, warp = tid >> 5;

    float v[4];
    float mx = -INFINITY;
    #pragma unroll
    for (int i = 0; i < 4; i++) {
        v[i] = row[tid + i * 256];
        mx = fmaxf(mx, v[i]);
    }
    #pragma unroll
    for (int off = 16; off > 0; off >>= 1)
        mx = fmaxf(mx, __shfl_xor_sync(0xffffffffu, mx, off));
    if (lane == 0) sred[warp] = mx;
    __syncthreads();
    if (tid == 0) {
        float m = sred[0];
        #pragma unroll
        for (int i = 1; i < 8; i++) m = fmaxf(m, sred[i]);
        sbc = m;
    }
    __syncthreads();
    const float gmx = sbc;

    float s = 0.0f;
    #pragma unroll
    for (int i = 0; i < 4; i++) {
        float e = expf(v[i] - gmx);
        sv[tid + i * 256] = e;
        s += e;
    }
    #pragma unroll
    for (int off = 16; off > 0; off >>= 1)
        s += __shfl_xor_sync(0xffffffffu, s, off);
    if (lane == 0) sred[warp] = s;
    __syncthreads();
    if (tid == 0) {
        float tt = 0.0f;
        #pragma unroll
        for (int i = 0; i < 8; i++) tt += sred[i];
        sbc = 1.0f / tt;
    }
    __syncthreads();
    const float inv = sbc;

    #pragma unroll
    for (int i = 0; i < 4; i++)
        crow[tid + i * 256] = round_tf(sv[tid + i * 256] * inv);

    #pragma unroll
    for (int e = warp * 2; e < warp * 2 + 2; e++) {
        float s2 = sv[e * 64 + lane] + sv[e * 64 + 32 + lane];
        #pragma unroll
        for (int off = 16; off > 0; off >>= 1)
            s2 += __shfl_xor_sync(0xffffffffu, s2, off);
        if (lane == 0) sprob[e] = s2 * inv * (1.0f / 64.0f);
    }
    __syncthreads();
    if (prob && tid < cE) prob[bm * cE + tid] = sprob[tid];
    if (top && tid == 0) {
        float best = -INFINITY;
        int bi = 0;
        #pragma unroll
        for (int e = 0; e < cE; e++) {
            if (sprob[e] > best) { best = sprob[e]; bi = e; }
        }
        top[bm] = (float)bi;
    }
}

// ---------------------------------------------------------------------------
// Host-side launch
// ---------------------------------------------------------------------------
extern "C" void kernel_launch(void* const* d_in, const int* in_sizes, int n_in,
                              void* d_out, int out_size)
{
    const float* x   = (const float*)d_in[0];  // [B, M, D]
    const float* phi = (const float*)d_in[1];  // [D, EP]
    const float* W1  = (const float*)d_in[2];  // [E, D, F]
    const float* b1  = (const float*)d_in[3];  // [E, F]
    const float* W2  = (const float*)d_in[4];  // [E, F, D]
    const float* b2  = (const float*)d_in[5];  // [E, D]
    float* out = (float*)d_out;

    float *logits, *dispatchp, *combinep, *mixp, *eoutp, *hidfb;
    cudaGetSymbolAddress((void**)&logits,    g_logits);
    cudaGetSymbolAddress((void**)&dispatchp, g_dispatch);
    cudaGetSymbolAddress((void**)&combinep,  g_combine);
    cudaGetSymbolAddress((void**)&mixp,      g_mix);
    cudaGetSymbolAddress((void**)&eoutp,     g_eout);
    cudaGetSymbolAddress((void**)&hidfb,     g_hid_fb);

    const bool full = ((long long)out_size >= SZ_FULL);
    float* hidp  = full ? (out + SZ_OUT + SZ_PROB + SZ_TOP) : hidfb;
    float* probp = full ? (out + SZ_OUT) : nullptr;
    float* topp  = full ? (out + SZ_OUT + SZ_PROB) : nullptr;

    // 1) logits = X[4096,768] @ phi[768,1024]  — 3xTF32 split (fp32-grade)
    gemm_tc<false, 0, true, true, true, false>
        <<<dim3(cEP / TBN, (cB * cM) / TBM, 1), 256>>>(
        x, phi, logits, nullptr, cB * cM, cEP, cD,
        0, 0, 0, 0, 0);

    // 2) dispatch = softmax over tokens (tf32-rounded output)
    dispatch_softmax_kernel<<<dim3(cEP / 32, cB), dim3(32, 8)>>>(logits, dispatchp);

    // 3) combine = softmax over (e,p) (rounded) + probabilities + argmax
    combine_softmax_kernel<<<dim3(cM, cB), 256>>>(logits, combinep, probp, topp);

    // 4) mix[b,ep,d] = dispatch[b]^T @ x[b]; A pre-rounded, B inline cvt;
    //    epilogue rounds mix to tf32.
    gemm_tc<true, 0, false, false, true, true>
        <<<dim3(cD / TBN, cEP / TBM, cB), 256>>>(
        dispatchp, x, mixp, nullptr, cEP, cD, cM,
        (long long)cM * cEP, (long long)cM * cD, (long long)cEP * cD, 0, 0);

    // 5) hidden = gelu(mix @ W1 + b1); z=expert, M=256 (4 batches merged).
    //    Single tf32-rounded store: serves as output AND stage-6 input.
    gemm_tc<false, 1, false, false, true, true>
        <<<dim3(cF / TBN, (cB * cP) / TBM, cE), 256>>>(
        mixp, W1, hidp, b1, cB * cP, cF, cD,
        0, (long long)cD * cF, 0, (long long)cF, cE);

    // 6) eout = hidden @ W2 + b2; z=expert, M=256; A pre-rounded; epilogue
    //    rounds eout to tf32.
    gemm_tc<false, 0, false, false, true, true>
        <<<dim3(cD / TBN, (cB * cP) / TBM, cE), 256>>>(
        hidp, W2, eoutp, b2, cB * cP, cD, cF,
        0, (long long)cF * cD, 0, (long long)cD, cE);

    // 7) outputs = combine[b] @ eout[b]  (both pre-rounded; no cvt at all)
    gemm_tc<false, 0, false, false, false, false>
        <<<dim3(cD / TBN, cM / TBM, cB), 256>>>(
        combinep, eoutp, out, nullptr, cM, cD, cEP,
        (long long)cM * cEP, (long long)cEP * cD, (long long)cM * cD, 0, 0);
}

// round 12
// speedup vs baseline: 1.1064x; 1.1064x over previous
#include <cuda_runtime.h>
#include <math.h>
#include <stdint.h>

// ---------------------------------------------------------------------------
// SoftMoE forward, tensor-core tf32 (m16n8k8, fp32 accum).
// Occupancy-first tiling: 32x32 warp tiles, 3 CTAs/SM, >=384 CTAs per GEMM.
// Operands pre-rounded to tf32 where free (softmax/GEMM epilogues).
// Logits GEMM keeps the 3xTF32 split (fp32-grade) to protect argmax outputs.
// B=4, M=1024, D=768, E=16, P=64, F=3072.
// ---------------------------------------------------------------------------

namespace cfg {
constexpr int cB = 4, cM = 1024, cD = 768, cE = 16, cP = 64, cF = 3072;
constexpr int cEP = cE * cP;  // 1024
constexpr long long SZ_OUT  = (long long)cB * cM * cD;
constexpr long long SZ_PROB = (long long)cB * cM * cE;
constexpr long long SZ_TOP  = (long long)cB * cM;
constexpr long long SZ_HID  = (long long)cB * cE * cP * cF;
constexpr long long SZ_FULL = SZ_OUT + SZ_PROB + SZ_TOP + SZ_HID;
}
using namespace cfg;

// Scratch (allocation-free: __device__ globals).
__device__ float g_logits  [(size_t)cB * cM * cEP];
__device__ float g_dispatch[(size_t)cB * cM * cEP];
__device__ float g_combine [(size_t)cB * cM * cEP];
__device__ float g_mix     [(size_t)cB * cE * cP * cD];
__device__ float g_eout    [(size_t)cB * cE * cP * cD];
__device__ float g_hid_fb  [(size_t)cB * cE * cP * cF];  // fallback hidden

// ---------------------------------------------------------------------------
// PTX helpers
// ---------------------------------------------------------------------------
__device__ __forceinline__ void cp_async16(void* s, const void* g) {
    unsigned sa = (unsigned)__cvta_generic_to_shared(s);
    asm volatile("cp.async.ca.shared.global [%0], [%1], 16;\n" :: "r"(sa), "l"(g));
}
__device__ __forceinline__ void cp_async4(void* s, const void* g) {
    unsigned sa = (unsigned)__cvta_generic_to_shared(s);
    asm volatile("cp.async.ca.shared.global [%0], [%1], 4;\n" :: "r"(sa), "l"(g));
}
__device__ __forceinline__ void cp_commit() {
    asm volatile("cp.async.commit_group;\n");
}
template <int N>
__device__ __forceinline__ void cp_wait() {
    asm volatile("cp.async.wait_group %0;\n" :: "n"(N));
}

__device__ __forceinline__ uint32_t f2tf(float x) {
    uint32_t u;
    asm("cvt.rna.tf32.f32 %0, %1;" : "=r"(u) : "f"(x));
    return u;
}
__device__ __forceinline__ float round_tf(float x) {
    return __uint_as_float(f2tf(x));
}

__device__ __forceinline__ void mma_tf32(float c[4], const uint32_t a[4],
                                         const uint32_t b[2]) {
    asm volatile(
        "mma.sync.aligned.m16n8k8.row.col.f32.tf32.tf32.f32 "
        "{%0,%1,%2,%3}, {%4,%5,%6,%7}, {%8,%9}, {%0,%1,%2,%3};\n"
        : "+f"(c[0]), "+f"(c[1]), "+f"(c[2]), "+f"(c[3])
        : "r"(a[0]), "r"(a[1]), "r"(a[2]), "r"(a[3]),
          "r"(b[0]), "r"(b[1]));
}

__device__ __forceinline__ float gelu_tanh(float x) {
    float x3 = x * x * x;
    return 0.5f * x * (1.0f + tanhf(0.7978845608028654f * (x + 0.044715f * x3)));
}

// ---------------------------------------------------------------------------
// Tensor-core GEMM: C[Md,Nd] = op(A)[Md,Kd] * B[Kd,Nd] (+bias) (+gelu)
//   TM x TN CTA tile (TM*TN = 8192), TK=16. 256 threads = 8 warps, each a
//   32x32 warp tile (MI=2 m16 x NI=4 n8). 32 acc regs/thread -> 3 CTAs/SM.
// op(A)=A   row-major [Md,Kd]          when !TRANSA
// op(A)=A^T with A row-major [Kd,Md]   when TRANSA (Md is the row stride)
// SPLIT: 3xTF32 error-compensated pass (fp32-grade accuracy).
// ACVT/BCVT: inline cvt to tf32; false = operand pre-rounded (feed raw bits).
// ROUND: round C to tf32 in the epilogue (post-bias/activation).
// Batched over blockIdx.z: r = z % zdiv, g = z / zdiv;
//   A += r*sA_r + g*sA_g; B += g*sB_g; C += r*sC_r + g*sC_g; bias += g*sBias_g.
// ---------------------------------------------------------------------------
#define TBK 16

template <int TM, int TN, bool TRANSA, int ACT, bool SPLIT, bool ACVT,
          bool BCVT, bool ROUND>
__global__ void __launch_bounds__(256, SPLIT ? 2 : 3) gemm_tc(
    const float* __restrict__ A, const float* __restrict__ B,
    float* __restrict__ C, const float* __restrict__ bias,
    int Md, int Nd, int Kd,
    long long sA_r, long long sA_g, long long sB_g,
    long long sC_r, long long sC_g, long long sBias_g,
    int zdiv)
{
    constexpr int MI = 2;            // m16 tiles per warp (warp M = 32)
    constexpr int NI = 4;            // n8 tiles per warp (warp N = 32)
    constexpr int WARPS_M = TM / 32;
    constexpr int SAS = TM + 8;
    constexpr int SBS = TN + 8;

    const int z = blockIdx.z;
    const int rb = z % zdiv, gg = z / zdiv;
    A += (long long)rb * sA_r + (long long)gg * sA_g;
    B += (long long)gg * sB_g;
    C += (long long)rb * sC_r + (long long)gg * sC_g;
    if (bias) bias += (long long)gg * sBias_g;

    __shared__ float As[2][TBK][SAS];
    __shared__ float Bs[2][TBK][SBS];

    const int tid  = threadIdx.x;
    const int lane = tid & 31, warp = tid >> 5;
    const int t  = lane & 3;
    const int gq = lane >> 2;
    const int wm = warp % WARPS_M, wn = warp / WARPS_M;
    const int m_base = wm * 32;
    const int n_base = wn * 32;
    const int row0 = blockIdx.y * TM;
    const int col0 = blockIdx.x * TN;

    auto loadA = [&](int buf, int k0) {
        if (!TRANSA) {
            #pragma unroll
            for (int i = 0; i < (TM * TBK) / 256; i++) {
                int l = tid + i * 256;
                int kk = l & 15, mm = l >> 4;
                cp_async4(&As[buf][kk][mm],
                          &A[(long long)(row0 + mm) * Kd + (k0 + kk)]);
            }
        } else {
            #pragma unroll
            for (int i = 0; i < (TM * TBK) / 1024; i++) {
                int l = tid * 4 + i * 1024;
                int ii = l % TM, kk = l / TM;
                cp_async16(&As[buf][kk][ii],
                           &A[(long long)(k0 + kk) * Md + (row0 + ii)]);
            }
        }
    };
    auto loadB = [&](int buf, int k0) {
        #pragma unroll
        for (int i = 0; i < (TN * TBK) / 1024; i++) {
            int l = tid * 4 + i * 1024;
            int nn = l % TN, kk = l / TN;
            cp_async16(&Bs[buf][kk][nn],
                       &B[(long long)(k0 + kk) * Nd + (col0 + nn)]);
        }
    };

    float acc[MI][NI][4];
    #pragma unroll
    for (int i = 0; i < MI; i++)
        #pragma unroll
        for (int j = 0; j < NI; j++)
            #pragma unroll
            for (int q = 0; q < 4; q++) acc[i][j][q] = 0.0f;

    loadA(0, 0);
    loadB(0, 0);
    cp_commit();

    const int nk = Kd / TBK;
    int buf = 0;
    for (int it = 0; it < nk; it++) {
        if (it + 1 < nk) {
            loadA(buf ^ 1, (it + 1) * TBK);
            loadB(buf ^ 1, (it + 1) * TBK);
            cp_commit();
            cp_wait<1>();
        } else {
            cp_wait<0>();
        }
        __syncthreads();

        #pragma unroll
        for (int ks = 0; ks < TBK; ks += 8) {
            uint32_t Ah[MI][4], Bh[NI][2];
            uint32_t Al[MI][4], Bl[NI][2];

            #pragma unroll
            for (int mi = 0; mi < MI; mi++) {
                const int m0 = m_base + mi * 16;
                float v[4];
                v[0] = As[buf][ks + t    ][m0 + gq];
                v[1] = As[buf][ks + t    ][m0 + gq + 8];
                v[2] = As[buf][ks + t + 4][m0 + gq];
                v[3] = As[buf][ks + t + 4][m0 + gq + 8];
                #pragma unroll
                for (int q = 0; q < 4; q++) {
                    Ah[mi][q] = (ACVT || SPLIT) ? f2tf(v[q])
                                                : __float_as_uint(v[q]);
                    if (SPLIT)
                        Al[mi][q] = f2tf(v[q] - __uint_as_float(Ah[mi][q]));
                }
            }
            #pragma unroll
            for (int ni = 0; ni < NI; ni++) {
                const int n0 = n_base + ni * 8;
                float u0 = Bs[buf][ks + t    ][n0 + gq];
                float u1 = Bs[buf][ks + t + 4][n0 + gq];
                Bh[ni][0] = (BCVT || SPLIT) ? f2tf(u0) : __float_as_uint(u0);
                Bh[ni][1] = (BCVT || SPLIT) ? f2tf(u1) : __float_as_uint(u1);
                if (SPLIT) {
                    Bl[ni][0] = f2tf(u0 - __uint_as_float(Bh[ni][0]));
                    Bl[ni][1] = f2tf(u1 - __uint_as_float(Bh[ni][1]));
                }
            }

            #pragma unroll
            for (int mi = 0; mi < MI; mi++)
                #pragma unroll
                for (int ni = 0; ni < NI; ni++) {
                    if (SPLIT) {
                        mma_tf32(acc[mi][ni], Ah[mi], Bl[ni]);
                        mma_tf32(acc[mi][ni], Al[mi], Bh[ni]);
                    }
                    mma_tf32(acc[mi][ni], Ah[mi], Bh[ni]);
                }
        }
        __syncthreads();
        buf ^= 1;
    }

    // Epilogue: c0,c1 at (r, 2t/2t+1); c2,c3 at (r+8, same cols)
    #pragma unroll
    for (int mi = 0; mi < MI; mi++) {
        const int r1 = row0 + m_base + mi * 16 + gq;
        #pragma unroll
        for (int ni = 0; ni < NI; ni++) {
            const int cg = col0 + n_base + ni * 8 + 2 * t;
            float b0 = 0.0f, b1 = 0.0f;
            if (bias) { b0 = bias[cg]; b1 = bias[cg + 1]; }
            float v0 = acc[mi][ni][0] + b0;
            float v1 = acc[mi][ni][1] + b1;
            float v2 = acc[mi][ni][2] + b0;
            float v3 = acc[mi][ni][3] + b1;
            if (ACT == 1) {
                v0 = gelu_tanh(v0); v1 = gelu_tanh(v1);
                v2 = gelu_tanh(v2); v3 = gelu_tanh(v3);
            }
            if (ROUND) {
                v0 = round_tf(v0); v1 = round_tf(v1);
                v2 = round_tf(v2); v3 = round_tf(v3);
            }
            *reinterpret_cast<float2*>(&C[(long long)r1 * Nd + cg]) =
                make_float2(v0, v1);
            *reinterpret_cast<float2*>(&C[(long long)(r1 + 8) * Nd + cg]) =
                make_float2(v2, v3);
        }
    }
}

// ---------------------------------------------------------------------------
// dispatch = softmax over tokens m (axis 1); output tf32-rounded.
// ---------------------------------------------------------------------------
__global__ __launch_bounds__(256) void dispatch_softmax_kernel(
    const float* __restrict__ logits, float* __restrict__ dispatch)
{
    const int b = blockIdx.y;
    const int ep = blockIdx.x * 32 + threadIdx.x;
    const int tx = threadIdx.x, ty = threadIdx.y;
    const float* base = logits + (long long)b * cM * cEP + ep;
    float* obase = dispatch + (long long)b * cM * cEP + ep;

    float mx = -INFINITY, s = 0.0f;
    for (int m = ty; m < cM; m += 8) {
        float v = base[(long long)m * cEP];
        float nm = fmaxf(mx, v);
        s = s * expf(mx - nm) + expf(v - nm);
        mx = nm;
    }
    __shared__ float smx[8][32], ssum[8][32];
    smx[ty][tx] = mx;
    ssum[ty][tx] = s;
    __syncthreads();
    if (ty == 0) {
        float M_ = smx[0][tx], S = ssum[0][tx];
        #pragma unroll
        for (int i = 1; i < 8; i++) {
            float m2 = smx[i][tx];
            float nm = fmaxf(M_, m2);
            S = S * expf(M_ - nm) + ssum[i][tx] * expf(m2 - nm);
            M_ = nm;
        }
        smx[0][tx] = M_;
        ssum[0][tx] = 1.0f / S;
    }
    __syncthreads();
    const float gmx = smx[0][tx];
    const float inv = ssum[0][tx];
    for (int m = ty; m < cM; m += 8)
        obase[(long long)m * cEP] =
            round_tf(expf(base[(long long)m * cEP] - gmx) * inv);
}

// ---------------------------------------------------------------------------
// combine = softmax over ep (tf32-rounded) + probabilities + argmax (fp32).
// ---------------------------------------------------------------------------
__global__ __launch_bounds__(256) void combine_softmax_kernel(
    const float* __restrict__ logits, float* __restrict__ combine,
    float* __restrict__ prob, float* __restrict__ top)
{
    const long long bm = blockIdx.y * gridDim.x + blockIdx.x;
    const float* row = logits + bm * cEP;
    float* crow = combine + bm * cEP;

    __shared__ float sv[cEP];
    __shared__ float sred[8];
    __shared__ float sbc;
    __shared__ float sprob[cE];

    const int tid = threadIdx.x;
    const int lane = tid & 31, warp = tid >> 5;

    float v[4];
    float mx = -INFINITY;
    #pragma unroll
    for (int i = 0; i < 4; i++) {
        v[i] = row[tid + i * 256];
        mx = fmaxf(mx, v[i]);
    }
    #pragma unroll
    for (int off = 16; off > 0; off >>= 1)
        mx = fmaxf(mx, __shfl_xor_sync(0xffffffffu, mx, off));
    if (lane == 0) sred[warp] = mx;
    __syncthreads();
    if (tid == 0) {
        float m = sred[0];
        #pragma unroll
        for (int i = 1; i < 8; i++) m = fmaxf(m, sred[i]);
        sbc = m;
    }
    __syncthreads();
    const float gmx = sbc;

    float s = 0.0f;
    #pragma unroll
    for (int i = 0; i < 4; i++) {
        float e = expf(v[i] - gmx);
        sv[tid + i * 256] = e;
        s += e;
    }
    #pragma unroll
    for (int off = 16; off > 0; off >>= 1)
        s += __shfl_xor_sync(0xffffffffu, s, off);
    if (lane == 0) sred[warp] = s;
    __syncthreads();
    if (tid == 0) {
        float tt = 0.0f;
        #pragma unroll
        for (int i = 0; i < 8; i++) tt += sred[i];
        sbc = 1.0f / tt;
    }
    __syncthreads();
    const float inv = sbc;

    #pragma unroll
    for (int i = 0; i < 4; i++)
        crow[tid + i * 256] = round_tf(sv[tid + i * 256] * inv);

    #pragma unroll
    for (int e = warp * 2; e < warp * 2 + 2; e++) {
        float s2 = sv[e * 64 + lane] + sv[e * 64 + 32 + lane];
        #pragma unroll
        for (int off = 16; off > 0; off >>= 1)
            s2 += __shfl_xor_sync(0xffffffffu, s2, off);
        if (lane == 0) sprob[e] = s2 * inv * (1.0f / 64.0f);
    }
    __syncthreads();
    if (prob && tid < cE) prob[bm * cE + tid] = sprob[tid];
    if (top && tid == 0) {
        float best = -INFINITY;
        int bi = 0;
        #pragma unroll
        for (int e = 0; e < cE; e++) {
            if (sprob[e] > best) { best = sprob[e]; bi = e; }
        }
        top[bm] = (float)bi;
    }
}

// ---------------------------------------------------------------------------
// Host-side launch
// ---------------------------------------------------------------------------
extern "C" void kernel_launch(void* const* d_in, const int* in_sizes, int n_in,
                              void* d_out, int out_size)
{
    const float* x   = (const float*)d_in[0];  // [B, M, D]
    const float* phi = (const float*)d_in[1];  // [D, EP]
    const float* W1  = (const float*)d_in[2];  // [E, D, F]
    const float* b1  = (const float*)d_in[3];  // [E, F]
    const float* W2  = (const float*)d_in[4];  // [E, F, D]
    const float* b2  = (const float*)d_in[5];  // [E, D]
    float* out = (float*)d_out;

    float *logits, *dispatchp, *combinep, *mixp, *eoutp, *hidfb;
    cudaGetSymbolAddress((void**)&logits,    g_logits);
    cudaGetSymbolAddress((void**)&dispatchp, g_dispatch);
    cudaGetSymbolAddress((void**)&combinep,  g_combine);
    cudaGetSymbolAddress((void**)&mixp,      g_mix);
    cudaGetSymbolAddress((void**)&eoutp,     g_eout);
    cudaGetSymbolAddress((void**)&hidfb,     g_hid_fb);

    const bool full = ((long long)out_size >= SZ_FULL);
    float* hidp  = full ? (out + SZ_OUT + SZ_PROB + SZ_TOP) : hidfb;
    float* probp = full ? (out + SZ_OUT) : nullptr;
    float* topp  = full ? (out + SZ_OUT + SZ_PROB) : nullptr;

    // 1) logits = X[4096,768] @ phi[768,1024]  — 3xTF32 split (fp32-grade)
    //    TM=128, TN=64 -> grid (16, 32) = 512 CTAs
    gemm_tc<128, 64, false, 0, true, true, true, false>
        <<<dim3(cEP / 64, (cB * cM) / 128, 1), 256>>>(
        x, phi, logits, nullptr, cB * cM, cEP, cD,
        0, 0, 0, 0, 0, 0, 1);

    // 2) dispatch = softmax over tokens (tf32-rounded output)
    dispatch_softmax_kernel<<<dim3(cEP / 32, cB), dim3(32, 8)>>>(logits, dispatchp);

    // 3) combine = softmax over (e,p) (rounded) + probabilities + argmax
    combine_softmax_kernel<<<dim3(cM, cB), 256>>>(logits, combinep, probp, topp);

    // 4) mix[b,ep,d] = dispatch[b]^T @ x[b]; A pre-rounded, B inline cvt;
    //    epilogue rounds. TM=128, TN=64 -> grid (12, 8, 4) = 384 CTAs
    gemm_tc<128, 64, true, 0, false, false, true, true>
        <<<dim3(cD / 64, cEP / 128, cB), 256>>>(
        dispatchp, x, mixp, nullptr, cEP, cD, cM,
        0, (long long)cM * cEP, (long long)cM * cD,
        0, (long long)cEP * cD, 0, 1);

    // 5) hidden = gelu(mix @ W1 + b1); per (b,e), z e-major (W1 L2 reuse).
    //    TM=64, TN=128 -> grid (24, 1, 64) = 1536 CTAs. Single tf32-rounded
    //    store serves as output AND stage-6 input.
    gemm_tc<64, 128, false, 1, false, false, true, true>
        <<<dim3(cF / 128, cP / 64, cB * cE), 256>>>(
        mixp, W1, hidp, b1, cP, cF, cD,
        (long long)cE * cP * cD, (long long)cP * cD, (long long)cD * cF,
        (long long)cE * cP * cF, (long long)cP * cF, (long long)cF, cB);

    // 6) eout = hidden @ W2 + b2; per (b,e); A pre-rounded; epilogue rounds.
    //    TM=64, TN=128 -> grid (6, 1, 64) = 384 CTAs
    gemm_tc<64, 128, false, 0, false, false, true, true>
        <<<dim3(cD / 128, cP / 64, cB * cE), 256>>>(
        hidp, W2, eoutp, b2, cP, cD, cF,
        (long long)cE * cP * cF, (long long)cP * cF, (long long)cF * cD,
        (long long)cE * cP * cD, (long long)cP * cD, (long long)cD, cB);

    // 7) outputs = combine[b] @ eout[b]  (both pre-rounded; no cvt)
    //    TM=128, TN=64 -> grid (12, 8, 4) = 384 CTAs
    gemm_tc<128, 64, false, 0, false, false, false, false>
        <<<dim3(cD / 64, cM / 128, cB), 256>>>(
        combinep, eoutp, out, nullptr, cM, cD, cEP,
        0, (long long)cM * cEP, (long long)cEP * cD,
        0, (long long)cM * cD, 0, 1);
}